// round 6
// baseline (speedup 1.0000x reference)
#include <cuda_runtime.h>
#include <cuda_bf16.h>
#include <stdint.h>

#define N_NODES 100000
#define N_EDGES 1600000
#define NUM_RELS 8
#define H_DIM 64
#define K_TOT 512
#define NSEG (N_NODES * NUM_RELS)          // 800000
#define NLDA 72
#define EDGE_CAP 2944
#define NB_SM 782                           // (N_NODES+127)/128
#define NB_PREPW 256                        // 65536/256
#define NB_HIST 6250                        // N_EDGES/256
#define SCAN_NB 782                         // ceil(NSEG/1024)

// ---------------- scratch ----------------
__device__ float g_x[(size_t)N_NODES * H_DIM];
__device__ float g_h[(size_t)N_NODES * H_DIM];
__device__ int   g_cnt[SCAN_NB * 1024];     // zero-init; re-zeroed by scan each run
__device__ int   g_rowptr[NSEG + 1];
__device__ int   g_wp[NSEG];
__device__ unsigned long long g_flags[SCAN_NB];  // zero-init; re-zeroed by scatter
__device__ int   g_esrc[N_EDGES];
__device__ float g_enorm[N_EDGES];
__device__ __nv_bfloat16 g_Wth[2 * H_DIM * K_TOT];
__device__ __nv_bfloat16 g_Wtl[2 * H_DIM * K_TOT];

// ---------------- helpers ----------------
__device__ __forceinline__ void mma16816(float* c, const uint32_t* a, const uint32_t* b) {
    asm volatile(
        "mma.sync.aligned.m16n8k16.row.col.f32.bf16.bf16.f32 "
        "{%0,%1,%2,%3}, {%4,%5,%6,%7}, {%8,%9}, {%0,%1,%2,%3};\n"
        : "+f"(c[0]), "+f"(c[1]), "+f"(c[2]), "+f"(c[3])
        : "r"(a[0]), "r"(a[1]), "r"(a[2]), "r"(a[3]), "r"(b[0]), "r"(b[1]));
}

__device__ __forceinline__ void split_bf16(float v, __nv_bfloat16& hi, __nv_bfloat16& lo) {
    hi = __float2bfloat16(v);
    lo = __float2bfloat16(v - __bfloat162float(hi));
}

// ---------------- size matcher body (256 threads/block) ----------------
__device__ void sm_body(int bid, const int* __restrict__ feat, const float* __restrict__ emb,
                        const float* __restrict__ smw, const float* __restrict__ smb,
                        char* smraw) {
    __nv_bfloat16* Ahi = (__nv_bfloat16*)smraw;
    __nv_bfloat16* Alo = Ahi + 128 * NLDA;
    __nv_bfloat16* Bhi = Alo + 128 * NLDA;
    __nv_bfloat16* Blo = Bhi + 64 * NLDA;
    int* sfeat = (int*)(Blo + 64 * NLDA);

    int tid = threadIdx.x;
    int rb = bid * 128;

    for (int idx = tid; idx < 128 * 8; idx += 256) {
        int r = idx >> 3, j = idx & 7;
        sfeat[idx] = (rb + r < N_NODES) ? feat[(size_t)(rb + r) * 8 + j] : 0;
    }

    int lane = tid & 31, warp = tid >> 5;
    int wr = (warp >> 2) * 64;
    int wc = (warp & 3) * 16;
    int g = lane >> 2, t = lane & 3;

    float C[8][4];
    #pragma unroll
    for (int i = 0; i < 8; i++)
        #pragma unroll
        for (int j = 0; j < 4; j++) C[i][j] = 0.f;

    for (int kc = 0; kc < 4; kc++) {
        __syncthreads();
        for (int idx = tid; idx < 128 * 64; idx += 256) {
            int r = idx >> 6, k = idx & 63;
            float v = 0.f;
            if (rb + r < N_NODES) {
                int fid = sfeat[r * 8 + kc * 2 + (k >> 5)];
                v = emb[(size_t)fid * 32 + (k & 31)];
            }
            __nv_bfloat16 h, l; split_bf16(v, h, l);
            Ahi[r * NLDA + k] = h; Alo[r * NLDA + k] = l;
        }
        for (int idx = tid; idx < 64 * 64; idx += 256) {
            int n = idx >> 6, k = idx & 63;
            float v = smw[n * 256 + kc * 64 + k];
            __nv_bfloat16 h, l; split_bf16(v, h, l);
            Bhi[n * NLDA + k] = h; Blo[n * NLDA + k] = l;
        }
        __syncthreads();

        #pragma unroll
        for (int ks = 0; ks < 4; ks++) {
            int k0 = ks * 16;
            #pragma unroll
            for (int p = 0; p < 3; p++) {
                const __nv_bfloat16* As = (p == 1) ? Alo : Ahi;
                const __nv_bfloat16* Bs = (p == 2) ? Blo : Bhi;
                uint32_t a[4][4], b[2][2];
                #pragma unroll
                for (int mt = 0; mt < 4; mt++) {
                    int r0 = wr + mt * 16;
                    a[mt][0] = *(const uint32_t*)(As + (r0 + g) * NLDA + k0 + 2 * t);
                    a[mt][1] = *(const uint32_t*)(As + (r0 + g + 8) * NLDA + k0 + 2 * t);
                    a[mt][2] = *(const uint32_t*)(As + (r0 + g) * NLDA + k0 + 8 + 2 * t);
                    a[mt][3] = *(const uint32_t*)(As + (r0 + g + 8) * NLDA + k0 + 8 + 2 * t);
                }
                #pragma unroll
                for (int nt = 0; nt < 2; nt++) {
                    int c0 = wc + nt * 8 + g;
                    b[nt][0] = *(const uint32_t*)(Bs + c0 * NLDA + k0 + 2 * t);
                    b[nt][1] = *(const uint32_t*)(Bs + c0 * NLDA + k0 + 8 + 2 * t);
                }
                #pragma unroll
                for (int mt = 0; mt < 4; mt++)
                    #pragma unroll
                    for (int nt = 0; nt < 2; nt++)
                        mma16816(C[mt * 2 + nt], a[mt], b[nt]);
            }
        }
    }

    #pragma unroll
    for (int mt = 0; mt < 4; mt++) {
        int r0 = rb + wr + mt * 16 + g;
        int r1 = r0 + 8;
        #pragma unroll
        for (int nt = 0; nt < 2; nt++) {
            int gc = wc + nt * 8 + 2 * t;
            float b0 = smb[gc], b1 = smb[gc + 1];
            if (r0 < N_NODES)
                *(float2*)(g_x + (size_t)r0 * 64 + gc) =
                    make_float2(C[mt * 2 + nt][0] + b0, C[mt * 2 + nt][1] + b1);
            if (r1 < N_NODES)
                *(float2*)(g_x + (size_t)r1 * 64 + gc) =
                    make_float2(C[mt * 2 + nt][2] + b0, C[mt * 2 + nt][3] + b1);
        }
    }
}

// ---------------- front kernel: sm + prepw + hist ----------------
__global__ void k_front(const int* __restrict__ feat, const float* __restrict__ emb,
                        const float* __restrict__ smw, const float* __restrict__ smb,
                        const float* __restrict__ V1, const float* __restrict__ c1,
                        const float* __restrict__ V2, const float* __restrict__ c2,
                        const int* __restrict__ dst, const int* __restrict__ etype) {
    extern __shared__ char smraw[];
    int bid = blockIdx.x;
    if (bid < NB_SM) {
        sm_body(bid, feat, emb, smw, smb, smraw);
    } else if (bid < NB_SM + NB_PREPW) {
        int t = (bid - NB_SM) * 256 + threadIdx.x;
        int sel = t >= H_DIM * K_TOT;
        int u = t & (H_DIM * K_TOT - 1);
        int o = u >> 9;
        int c = u & 511;
        int r = c >> 6, k = c & 63;
        const float* V = sel ? V2 : V1;
        const float* cp = sel ? c2 : c1;
        float s = 0.f;
        #pragma unroll
        for (int b = 0; b < 8; b++)
            s += cp[r * 8 + b] * V[(b * 64 + k) * 64 + o];
        __nv_bfloat16 hi = __float2bfloat16(s);
        __nv_bfloat16 lo = __float2bfloat16(s - __bfloat162float(hi));
        g_Wth[t] = hi;
        g_Wtl[t] = lo;
    } else {
        int e = (bid - NB_SM - NB_PREPW) * 256 + threadIdx.x;
        if (e < N_EDGES) atomicAdd(&g_cnt[dst[e] * NUM_RELS + etype[e]], 1);
    }
}

// ---------------- single-kernel scan (decoupled lookback) ----------------
__global__ __launch_bounds__(1024) void k_scan() {
    __shared__ int wsum[32];
    __shared__ int s_excl;
    int tid = threadIdx.x, b = blockIdx.x;
    int i = b * 1024 + tid;
    int v = (i < NSEG) ? g_cnt[i] : 0;
    int lane = tid & 31, wid = tid >> 5;
    int s = v;
    #pragma unroll
    for (int d = 1; d < 32; d <<= 1) {
        int t = __shfl_up_sync(0xFFFFFFFFu, s, d);
        if (lane >= d) s += t;
    }
    if (lane == 31) wsum[wid] = s;
    __syncthreads();
    if (wid == 0) {
        int ws = wsum[lane];
        #pragma unroll
        for (int d = 1; d < 32; d <<= 1) {
            int t = __shfl_up_sync(0xFFFFFFFFu, ws, d);
            if (lane >= d) ws += t;
        }
        wsum[lane] = ws;
    }
    __syncthreads();
    int incl = s + ((wid > 0) ? wsum[wid - 1] : 0);
    int total = wsum[31];

    if (tid == 0) {
        unsigned long long f =
            ((unsigned long long)((b == 0) ? 2u : 1u) << 32) | (unsigned)total;
        atomicExch(&g_flags[b], f);
        if (b == 0) s_excl = 0;
    }
    if (b > 0 && wid == 0) {
        int running = 0;
        int p = b - 1;
        while (true) {
            int idx = p - lane;
            unsigned long long f = (idx >= 0) ? atomicOr(&g_flags[idx], 0ULL)
                                              : (2ULL << 32);
            unsigned st = (unsigned)(f >> 32);
            if (__ballot_sync(0xFFFFFFFFu, st == 0)) continue;  // retry window
            unsigned b2 = __ballot_sync(0xFFFFFFFFu, st == 2);
            int val = (int)(unsigned)f;
            if (b2) {
                int k = __ffs(b2) - 1;         // nearest prefix
                int contrib = (lane <= k) ? val : 0;
                #pragma unroll
                for (int off = 16; off > 0; off >>= 1)
                    contrib += __shfl_xor_sync(0xFFFFFFFFu, contrib, off);
                running += contrib;
                break;
            } else {
                int contrib = val;
                #pragma unroll
                for (int off = 16; off > 0; off >>= 1)
                    contrib += __shfl_xor_sync(0xFFFFFFFFu, contrib, off);
                running += contrib;
                p -= 32;
            }
        }
        if (lane == 0) {
            s_excl = running;
            unsigned long long f = (2ULL << 32) | (unsigned)(running + total);
            atomicExch(&g_flags[b], f);
        }
    }
    __syncthreads();
    int rp = s_excl + incl - v;
    if (i < NSEG) {
        g_rowptr[i] = rp;
        g_wp[i] = rp;
        g_cnt[i] = 0;                     // restore zero for next run
    }
    if (i == NSEG - 1) g_rowptr[NSEG] = rp + v;
}

// ---------------- scatter (also re-zeroes g_flags) ----------------
__global__ void k_scatter(const int* __restrict__ src, const int* __restrict__ dst,
                          const int* __restrict__ etype, const float* __restrict__ norm) {
    int gid = blockIdx.x * blockDim.x + threadIdx.x;
    if (gid < SCAN_NB) g_flags[gid] = 0ULL;
    if (gid >= N_EDGES) return;
    int seg = dst[gid] * NUM_RELS + etype[gid];
    int p = atomicAdd(&g_wp[seg], 1);
    g_esrc[p] = src[gid];
    g_enorm[p] = norm[gid];
}

// ---------------- fused layer: batched-MLP aggregation + chunked MMA ---------------
__global__ __launch_bounds__(512, 2)
void k_fused(int phase, const float* __restrict__ bias, float* __restrict__ dout) {
    const float* __restrict__ X = phase ? g_h : g_x;
    float* __restrict__ OP = phase ? dout : g_h;
    const __nv_bfloat16* __restrict__ Wh = g_Wth + phase * H_DIM * K_TOT;
    const __nv_bfloat16* __restrict__ Wl = g_Wtl + phase * H_DIM * K_TOT;

    extern __shared__ char smraw[];
    __nv_bfloat16* Ahi = (__nv_bfloat16*)smraw;             // 128*72
    __nv_bfloat16* Alo = Ahi + 128 * NLDA;
    __nv_bfloat16* Bhi = Alo + 128 * NLDA;                  // 64*72
    __nv_bfloat16* Blo = Bhi + 64 * NLDA;
    int*  rps  = (int*)(Blo + 64 * NLDA);                   // 1025 (+3 pad)
    int2* sedge = (int2*)(rps + 1028);                      // EDGE_CAP

    int tid = threadIdx.x;
    int rb = blockIdx.x * 128;
    int lane = tid & 31, warp = tid >> 5;
    int c = lane * 2;

    for (int idx = tid; idx < 1025; idx += 512) {
        int gi = rb * NUM_RELS + idx;
        rps[idx] = g_rowptr[gi < NSEG ? gi : NSEG];
    }
    __syncthreads();
    int ebase = rps[0];
    int ecnt = rps[1024] - ebase;
    bool fits = (ecnt <= EDGE_CAP);

    if (fits) {
        for (int idx = tid; idx < ecnt; idx += 512)
            sedge[idx] = make_int2(g_esrc[ebase + idx],
                                   __float_as_int(g_enorm[ebase + idx]));
    }
    __syncthreads();

    int wr = (warp >> 2) * 32;
    int wc = (warp & 3) * 16;
    int g = lane >> 2, t = lane & 3;

    float C[4][4];
    #pragma unroll
    for (int i = 0; i < 4; i++)
        #pragma unroll
        for (int j = 0; j < 4; j++) C[i][j] = 0.f;

    for (int r = 0; r < NUM_RELS; r++) {
        if (r) __syncthreads();

        int ln0 = warp * 8;
        #pragma unroll
        for (int half = 0; half < 2; half++) {
            int base = ln0 + half * 4;
            int beg[4], cnt[4];
            #pragma unroll
            for (int i = 0; i < 4; i++) {
                int row = base + i;
                int bg = rps[row * NUM_RELS + r];
                beg[i] = bg - ebase;
                cnt[i] = rps[row * NUM_RELS + r + 1] - bg;
            }
            float ax[4] = {0.f, 0.f, 0.f, 0.f}, ay[4] = {0.f, 0.f, 0.f, 0.f};

            if (fits) {
                int jm = max(max(cnt[0], cnt[1]), max(cnt[2], cnt[3]));
                jm = min(jm, 4);
                for (int j = 0; j < jm; j++) {        // uniform loop
                    float2 v[4]; float nn[4];
                    #pragma unroll
                    for (int i = 0; i < 4; i++) {
                        int ec = cnt[i];
                        int e = beg[i] + ((j < ec) ? j : ((ec > 0) ? ec - 1 : 0));
                        e = min(e, EDGE_CAP - 1);
                        int2 sn = sedge[e];
                        nn[i] = (j < ec) ? __int_as_float(sn.y) : 0.f;
                        unsigned s = min((unsigned)sn.x, (unsigned)(N_NODES - 1));
                        v[i] = *(const float2*)(X + (size_t)s * 64 + c);
                    }
                    #pragma unroll
                    for (int i = 0; i < 4; i++) {
                        ax[i] = fmaf(nn[i], v[i].x, ax[i]);
                        ay[i] = fmaf(nn[i], v[i].y, ay[i]);
                    }
                }
                // rare tails (cnt > 4)
                #pragma unroll
                for (int i = 0; i < 4; i++) {
                    for (int e = beg[i] + 4, en = beg[i] + cnt[i]; e < en; e++) {
                        int2 sn = sedge[e];
                        float nf = __int_as_float(sn.y);
                        float2 v = *(const float2*)(X + (size_t)sn.x * 64 + c);
                        ax[i] = fmaf(nf, v.x, ax[i]);
                        ay[i] = fmaf(nf, v.y, ay[i]);
                    }
                }
            } else {
                // fallback: global metadata, sequential per node (never expected)
                #pragma unroll
                for (int i = 0; i < 4; i++) {
                    for (int e = beg[i] + ebase, en = e + cnt[i]; e < en; e++) {
                        int s0 = g_esrc[e];
                        float nf = g_enorm[e];
                        float2 v = *(const float2*)(X + (size_t)s0 * 64 + c);
                        ax[i] = fmaf(nf, v.x, ax[i]);
                        ay[i] = fmaf(nf, v.y, ay[i]);
                    }
                }
            }

            #pragma unroll
            for (int i = 0; i < 4; i++) {
                int row = base + i;
                __nv_bfloat16 h0, l0, h1, l1;
                split_bf16(ax[i], h0, l0);
                split_bf16(ay[i], h1, l1);
                __nv_bfloat162 ph; ph.x = h0; ph.y = h1;
                __nv_bfloat162 pl; pl.x = l0; pl.y = l1;
                *(__nv_bfloat162*)(Ahi + row * NLDA + c) = ph;
                *(__nv_bfloat162*)(Alo + row * NLDA + c) = pl;
            }
        }

        for (int idx = tid; idx < 64 * 64; idx += 512) {
            int n = idx >> 6, k = idx & 63;
            Bhi[n * NLDA + k] = Wh[n * K_TOT + r * 64 + k];
            Blo[n * NLDA + k] = Wl[n * K_TOT + r * 64 + k];
        }
        __syncthreads();

        #pragma unroll
        for (int ks = 0; ks < 4; ks++) {
            int k0 = ks * 16;
            #pragma unroll
            for (int p = 0; p < 3; p++) {
                const __nv_bfloat16* As = (p == 1) ? Alo : Ahi;
                const __nv_bfloat16* Bs = (p == 2) ? Blo : Bhi;
                uint32_t a[2][4], b[2][2];
                #pragma unroll
                for (int mt = 0; mt < 2; mt++) {
                    int r0 = wr + mt * 16;
                    a[mt][0] = *(const uint32_t*)(As + (r0 + g) * NLDA + k0 + 2 * t);
                    a[mt][1] = *(const uint32_t*)(As + (r0 + g + 8) * NLDA + k0 + 2 * t);
                    a[mt][2] = *(const uint32_t*)(As + (r0 + g) * NLDA + k0 + 8 + 2 * t);
                    a[mt][3] = *(const uint32_t*)(As + (r0 + g + 8) * NLDA + k0 + 8 + 2 * t);
                }
                #pragma unroll
                for (int nt = 0; nt < 2; nt++) {
                    int c0 = wc + nt * 8 + g;
                    b[nt][0] = *(const uint32_t*)(Bs + c0 * NLDA + k0 + 2 * t);
                    b[nt][1] = *(const uint32_t*)(Bs + c0 * NLDA + k0 + 8 + 2 * t);
                }
                #pragma unroll
                for (int mt = 0; mt < 2; mt++)
                    #pragma unroll
                    for (int nt = 0; nt < 2; nt++)
                        mma16816(C[mt * 2 + nt], a[mt], b[nt]);
            }
        }
    }

    int dorelu = (phase == 0);
    #pragma unroll
    for (int mt = 0; mt < 2; mt++) {
        int r0 = rb + wr + mt * 16 + g;
        int r1 = r0 + 8;
        #pragma unroll
        for (int nt = 0; nt < 2; nt++) {
            int gc = wc + nt * 8 + 2 * t;
            float b0 = bias[gc], b1 = bias[gc + 1];
            float c00 = C[mt * 2 + nt][0] + b0, c01 = C[mt * 2 + nt][1] + b1;
            float c10 = C[mt * 2 + nt][2] + b0, c11 = C[mt * 2 + nt][3] + b1;
            if (dorelu) {
                c00 = fmaxf(c00, 0.f); c01 = fmaxf(c01, 0.f);
                c10 = fmaxf(c10, 0.f); c11 = fmaxf(c11, 0.f);
            }
            if (r0 < N_NODES)
                *(float2*)(OP + (size_t)r0 * 64 + gc) = make_float2(c00, c01);
            if (r1 < N_NODES)
                *(float2*)(OP + (size_t)r1 * 64 + gc) = make_float2(c10, c11);
        }
    }
}

// ---------------- launch ----------------
extern "C" void kernel_launch(void* const* d_in, const int* in_sizes, int n_in,
                              void* d_out, int out_size) {
    const int* feat = (const int*)d_in[0];
    const int* src = (const int*)d_in[1];
    const int* dst = (const int*)d_in[2];
    const int* etype = (const int*)d_in[3];
    const float* norm = (const float*)d_in[4];
    const float* emb = (const float*)d_in[5];
    const float* smw = (const float*)d_in[6];
    const float* smb = (const float*)d_in[7];
    const float* V1 = (const float*)d_in[8];
    const float* c1 = (const float*)d_in[9];
    const float* b1 = (const float*)d_in[10];
    const float* V2 = (const float*)d_in[11];
    const float* c2 = (const float*)d_in[12];
    const float* b2 = (const float*)d_in[13];
    float* out = (float*)d_out;

    const int smemSM = (128 * NLDA * 2 + 64 * NLDA * 2) * 2 + 128 * 8 * 4;  // 59904... (55296+4096)
    const int smemFU = (128 * NLDA * 2 + 64 * NLDA * 2) * 2 + 1028 * 4 + EDGE_CAP * 8;
    static int attr_done = 0;
    if (!attr_done) {
        cudaFuncSetAttribute(k_front, cudaFuncAttributeMaxDynamicSharedMemorySize, smemSM);
        cudaFuncSetAttribute(k_fused, cudaFuncAttributeMaxDynamicSharedMemorySize, smemFU);
        attr_done = 1;
    }

    // launch 0: size matcher + weight prep + histogram (independent works)
    k_front<<<NB_SM + NB_PREPW + NB_HIST, 256, smemSM>>>(feat, emb, smw, smb,
                                                         V1, c1, V2, c2, dst, etype);
    // launch 1: single-pass scan (also re-zeroes g_cnt)
    k_scan<<<SCAN_NB, 1024>>>();
    // launch 2: scatter into CSR order (also re-zeroes g_flags)
    k_scatter<<<NB_HIST, 256>>>(src, dst, etype, norm);
    // launch 3 (ncu capture slot): fused layer 1
    k_fused<<<NB_SM, 512, smemFU>>>(0, b1, nullptr);
    // launch 4: fused layer 2
    k_fused<<<NB_SM, 512, smemFU>>>(1, b2, out);
}

// round 7
// speedup vs baseline: 1.7267x; 1.7267x over previous
#include <cuda_runtime.h>
#include <cuda_bf16.h>
#include <stdint.h>

#define N_NODES 100000
#define N_EDGES 1600000
#define NUM_RELS 8
#define H_DIM 64
#define K_TOT 512
#define NSEG (N_NODES * NUM_RELS)          // 800000
#define NLDA 72                            // bf16 elems; 144B row stride
#define NB_SM 782
#define NB_PREPW 256
#define NB_HIST 6250
#define SCAN_NB 782

// ---------------- scratch ----------------
__device__ float g_x[(size_t)N_NODES * H_DIM];
__device__ float g_h[(size_t)N_NODES * H_DIM];
__device__ int   g_cnt[SCAN_NB * 1024];     // zero-init; re-zeroed by scan each run
__device__ int   g_rowptr[NSEG + 1];
__device__ int   g_wp[NSEG];
__device__ unsigned long long g_flags[SCAN_NB];  // zero-init; re-zeroed by scatter
__device__ int2  g_emeta[N_EDGES];          // {src, norm-bits}, CSR order
__device__ __nv_bfloat16 g_Wth[2 * H_DIM * K_TOT];
__device__ __nv_bfloat16 g_Wtl[2 * H_DIM * K_TOT];

// ---------------- helpers ----------------
__device__ __forceinline__ void mma16816(float* c, const uint32_t* a, const uint32_t* b) {
    asm volatile(
        "mma.sync.aligned.m16n8k16.row.col.f32.bf16.bf16.f32 "
        "{%0,%1,%2,%3}, {%4,%5,%6,%7}, {%8,%9}, {%0,%1,%2,%3};\n"
        : "+f"(c[0]), "+f"(c[1]), "+f"(c[2]), "+f"(c[3])
        : "r"(a[0]), "r"(a[1]), "r"(a[2]), "r"(a[3]), "r"(b[0]), "r"(b[1]));
}

__device__ __forceinline__ void ldsm4(uint32_t* r, uint32_t addr) {
    asm volatile("ldmatrix.sync.aligned.m8n8.x4.shared.b16 {%0,%1,%2,%3}, [%4];"
        : "=r"(r[0]), "=r"(r[1]), "=r"(r[2]), "=r"(r[3]) : "r"(addr));
}

__device__ __forceinline__ void split_bf16(float v, __nv_bfloat16& hi, __nv_bfloat16& lo) {
    hi = __float2bfloat16(v);
    lo = __float2bfloat16(v - __bfloat162float(hi));
}

// ---------------- size matcher body (256 threads/block) ----------------
__device__ void sm_body(int bid, const int* __restrict__ feat, const float* __restrict__ emb,
                        const float* __restrict__ smw, const float* __restrict__ smb,
                        char* smraw) {
    __nv_bfloat16* Ahi = (__nv_bfloat16*)smraw;
    __nv_bfloat16* Alo = Ahi + 128 * NLDA;
    __nv_bfloat16* Bhi = Alo + 128 * NLDA;
    __nv_bfloat16* Blo = Bhi + 64 * NLDA;
    int* sfeat = (int*)(Blo + 64 * NLDA);

    int tid = threadIdx.x;
    int rb = bid * 128;

    for (int idx = tid; idx < 128 * 8; idx += 256) {
        int r = idx >> 3, j = idx & 7;
        sfeat[idx] = (rb + r < N_NODES) ? feat[(size_t)(rb + r) * 8 + j] : 0;
    }

    int lane = tid & 31, warp = tid >> 5;
    int wr = (warp >> 2) * 64;
    int wc = (warp & 3) * 16;
    int g = lane >> 2, t = lane & 3;

    float C[8][4];
    #pragma unroll
    for (int i = 0; i < 8; i++)
        #pragma unroll
        for (int j = 0; j < 4; j++) C[i][j] = 0.f;

    for (int kc = 0; kc < 4; kc++) {
        __syncthreads();
        for (int idx = tid; idx < 128 * 64; idx += 256) {
            int r = idx >> 6, k = idx & 63;
            float v = 0.f;
            if (rb + r < N_NODES) {
                int fid = sfeat[r * 8 + kc * 2 + (k >> 5)];
                v = emb[(size_t)fid * 32 + (k & 31)];
            }
            __nv_bfloat16 h, l; split_bf16(v, h, l);
            Ahi[r * NLDA + k] = h; Alo[r * NLDA + k] = l;
        }
        for (int idx = tid; idx < 64 * 64; idx += 256) {
            int n = idx >> 6, k = idx & 63;
            float v = smw[n * 256 + kc * 64 + k];
            __nv_bfloat16 h, l; split_bf16(v, h, l);
            Bhi[n * NLDA + k] = h; Blo[n * NLDA + k] = l;
        }
        __syncthreads();

        #pragma unroll
        for (int ks = 0; ks < 4; ks++) {
            int k0 = ks * 16;
            #pragma unroll
            for (int p = 0; p < 3; p++) {
                const __nv_bfloat16* As = (p == 1) ? Alo : Ahi;
                const __nv_bfloat16* Bs = (p == 2) ? Blo : Bhi;
                uint32_t a[4][4], b[2][2];
                #pragma unroll
                for (int mt = 0; mt < 4; mt++) {
                    int r0 = wr + mt * 16;
                    a[mt][0] = *(const uint32_t*)(As + (r0 + g) * NLDA + k0 + 2 * t);
                    a[mt][1] = *(const uint32_t*)(As + (r0 + g + 8) * NLDA + k0 + 2 * t);
                    a[mt][2] = *(const uint32_t*)(As + (r0 + g) * NLDA + k0 + 8 + 2 * t);
                    a[mt][3] = *(const uint32_t*)(As + (r0 + g + 8) * NLDA + k0 + 8 + 2 * t);
                }
                #pragma unroll
                for (int nt = 0; nt < 2; nt++) {
                    int c0 = wc + nt * 8 + g;
                    b[nt][0] = *(const uint32_t*)(Bs + c0 * NLDA + k0 + 2 * t);
                    b[nt][1] = *(const uint32_t*)(Bs + c0 * NLDA + k0 + 8 + 2 * t);
                }
                #pragma unroll
                for (int mt = 0; mt < 4; mt++)
                    #pragma unroll
                    for (int nt = 0; nt < 2; nt++)
                        mma16816(C[mt * 2 + nt], a[mt], b[nt]);
            }
        }
    }

    #pragma unroll
    for (int mt = 0; mt < 4; mt++) {
        int r0 = rb + wr + mt * 16 + g;
        int r1 = r0 + 8;
        #pragma unroll
        for (int nt = 0; nt < 2; nt++) {
            int gc = wc + nt * 8 + 2 * t;
            float b0 = smb[gc], b1 = smb[gc + 1];
            if (r0 < N_NODES)
                *(float2*)(g_x + (size_t)r0 * 64 + gc) =
                    make_float2(C[mt * 2 + nt][0] + b0, C[mt * 2 + nt][1] + b1);
            if (r1 < N_NODES)
                *(float2*)(g_x + (size_t)r1 * 64 + gc) =
                    make_float2(C[mt * 2 + nt][2] + b0, C[mt * 2 + nt][3] + b1);
        }
    }
}

// ---------------- front kernel: sm + prepw + hist ----------------
__global__ void k_front(const int* __restrict__ feat, const float* __restrict__ emb,
                        const float* __restrict__ smw, const float* __restrict__ smb,
                        const float* __restrict__ V1, const float* __restrict__ c1,
                        const float* __restrict__ V2, const float* __restrict__ c2,
                        const int* __restrict__ dst, const int* __restrict__ etype) {
    extern __shared__ char smraw[];
    int bid = blockIdx.x;
    if (bid < NB_SM) {
        sm_body(bid, feat, emb, smw, smb, smraw);
    } else if (bid < NB_SM + NB_PREPW) {
        int t = (bid - NB_SM) * 256 + threadIdx.x;
        int sel = t >= H_DIM * K_TOT;
        int u = t & (H_DIM * K_TOT - 1);
        int o = u >> 9;
        int c = u & 511;
        int r = c >> 6, k = c & 63;
        const float* V = sel ? V2 : V1;
        const float* cp = sel ? c2 : c1;
        float s = 0.f;
        #pragma unroll
        for (int b = 0; b < 8; b++)
            s += cp[r * 8 + b] * V[(b * 64 + k) * 64 + o];
        __nv_bfloat16 hi = __float2bfloat16(s);
        __nv_bfloat16 lo = __float2bfloat16(s - __bfloat162float(hi));
        g_Wth[t] = hi;
        g_Wtl[t] = lo;
    } else {
        int e = (bid - NB_SM - NB_PREPW) * 256 + threadIdx.x;
        if (e < N_EDGES)
            atomicAdd(&g_cnt[etype[e] * N_NODES + dst[e]], 1);
    }
}

// ---------------- single-kernel scan (decoupled lookback) ----------------
__global__ __launch_bounds__(1024) void k_scan() {
    __shared__ int wsum[32];
    __shared__ int s_excl;
    int tid = threadIdx.x, b = blockIdx.x;
    int i = b * 1024 + tid;
    int v = (i < NSEG) ? g_cnt[i] : 0;
    int lane = tid & 31, wid = tid >> 5;
    int s = v;
    #pragma unroll
    for (int d = 1; d < 32; d <<= 1) {
        int t = __shfl_up_sync(0xFFFFFFFFu, s, d);
        if (lane >= d) s += t;
    }
    if (lane == 31) wsum[wid] = s;
    __syncthreads();
    if (wid == 0) {
        int ws = wsum[lane];
        #pragma unroll
        for (int d = 1; d < 32; d <<= 1) {
            int t = __shfl_up_sync(0xFFFFFFFFu, ws, d);
            if (lane >= d) ws += t;
        }
        wsum[lane] = ws;
    }
    __syncthreads();
    int incl = s + ((wid > 0) ? wsum[wid - 1] : 0);
    int total = wsum[31];

    if (tid == 0) {
        unsigned long long f =
            ((unsigned long long)((b == 0) ? 2u : 1u) << 32) | (unsigned)total;
        atomicExch(&g_flags[b], f);
        if (b == 0) s_excl = 0;
    }
    if (b > 0 && wid == 0) {
        int running = 0;
        int p = b - 1;
        while (true) {
            int idx = p - lane;
            unsigned long long f = (idx >= 0) ? atomicOr(&g_flags[idx], 0ULL)
                                              : (2ULL << 32);
            unsigned st = (unsigned)(f >> 32);
            if (__ballot_sync(0xFFFFFFFFu, st == 0)) continue;
            unsigned b2 = __ballot_sync(0xFFFFFFFFu, st == 2);
            int val = (int)(unsigned)f;
            if (b2) {
                int k = __ffs(b2) - 1;
                int contrib = (lane <= k) ? val : 0;
                #pragma unroll
                for (int off = 16; off > 0; off >>= 1)
                    contrib += __shfl_xor_sync(0xFFFFFFFFu, contrib, off);
                running += contrib;
                break;
            } else {
                int contrib = val;
                #pragma unroll
                for (int off = 16; off > 0; off >>= 1)
                    contrib += __shfl_xor_sync(0xFFFFFFFFu, contrib, off);
                running += contrib;
                p -= 32;
            }
        }
        if (lane == 0) {
            s_excl = running;
            unsigned long long f = (2ULL << 32) | (unsigned)(running + total);
            atomicExch(&g_flags[b], f);
        }
    }
    __syncthreads();
    int rp = s_excl + incl - v;
    if (i < NSEG) {
        g_rowptr[i] = rp;
        g_wp[i] = rp;
        g_cnt[i] = 0;
    }
    if (i == NSEG - 1) g_rowptr[NSEG] = rp + v;
}

// ---------------- scatter (also re-zeroes g_flags) ----------------
__global__ void k_scatter(const int* __restrict__ src, const int* __restrict__ dst,
                          const int* __restrict__ etype, const float* __restrict__ norm) {
    int gid = blockIdx.x * blockDim.x + threadIdx.x;
    if (gid < SCAN_NB) g_flags[gid] = 0ULL;
    if (gid >= N_EDGES) return;
    int seg = etype[gid] * N_NODES + dst[gid];
    int p = atomicAdd(&g_wp[seg], 1);
    g_emeta[p] = make_int2(src[gid], __float_as_int(norm[gid]));
}

// ---------------- fused layer v3: reg-meta edge loop + smem RMW + ldmatrix ----------
__global__ __launch_bounds__(512, 2)
void k_fused(int phase, const float* __restrict__ bias, float* __restrict__ dout) {
    const float* __restrict__ X = phase ? g_h : g_x;
    float* __restrict__ OP = phase ? dout : g_h;
    const __nv_bfloat16* __restrict__ Wh = g_Wth + phase * H_DIM * K_TOT;
    const __nv_bfloat16* __restrict__ Wl = g_Wtl + phase * H_DIM * K_TOT;

    extern __shared__ char smraw[];
    __nv_bfloat16* Ahi = (__nv_bfloat16*)smraw;         // 128*72 (18432 B)
    __nv_bfloat16* Alo = Ahi + 128 * NLDA;              // 18432 B
    __nv_bfloat16* Bhi = Alo + 128 * NLDA;              // 64*72  (9216 B)
    __nv_bfloat16* Blo = Bhi + 64 * NLDA;               // 9216 B
    float* Aacc = (float*)(Blo + 64 * NLDA);            // 128*66 fp32 (33792 B)

    int tid = threadIdx.x;
    int rb = blockIdx.x * 128;
    int lane = tid & 31, warp = tid >> 5;
    int c = lane * 2;

    int wr = (warp >> 2) * 32;
    int wc = (warp & 3) * 16;
    int g = lane >> 2, t = lane & 3;

    // ldmatrix per-lane address bases
    int rowA = (lane & 7) + ((lane >> 3) & 1) * 8;      // within 16-row tile
    int colA = ((lane >> 4) & 1) * 8;                   // 0 or 8 (elems)
    int rowB = (lane & 7) + ((lane >> 4) & 1) * 8;
    int colB = ((lane >> 3) & 1) * 8;
    uint32_t aHiAddr = (uint32_t)__cvta_generic_to_shared(Ahi) + (wr + rowA) * (NLDA * 2) + colA * 2;
    uint32_t aLoAddr = (uint32_t)__cvta_generic_to_shared(Alo) + (wr + rowA) * (NLDA * 2) + colA * 2;
    uint32_t bHiAddr = (uint32_t)__cvta_generic_to_shared(Bhi) + (wc + rowB) * (NLDA * 2) + colB * 2;
    uint32_t bLoAddr = (uint32_t)__cvta_generic_to_shared(Blo) + (wc + rowB) * (NLDA * 2) + colB * 2;

    float C[4][4];
    #pragma unroll
    for (int i = 0; i < 4; i++)
        #pragma unroll
        for (int j = 0; j < 4; j++) C[i][j] = 0.f;

    float* arow = Aacc + (warp * 8) * 66;

    for (int r = 0; r < NUM_RELS; r++) {
        // ===== aggregation into warp-private Aacc rows (overlaps prior MMA) =====
        int segbase = r * N_NODES + rb + warp * 8;
        int clampmax = r * N_NODES + N_NODES;
        int bp = 0;
        if (lane <= 8) bp = g_rowptr[min(segbase + lane, clampmax)];
        int wbeg = __shfl_sync(0xFFFFFFFFu, bp, 0);
        int wend = __shfl_sync(0xFFFFFFFFu, bp, 8);
        int b1 = __shfl_sync(0xFFFFFFFFu, bp, 1);
        int b2 = __shfl_sync(0xFFFFFFFFu, bp, 2);
        int b3 = __shfl_sync(0xFFFFFFFFu, bp, 3);
        int b4 = __shfl_sync(0xFFFFFFFFu, bp, 4);
        int b5 = __shfl_sync(0xFFFFFFFFu, bp, 5);
        int b6 = __shfl_sync(0xFFFFFFFFu, bp, 6);
        int b7 = __shfl_sync(0xFFFFFFFFu, bp, 7);
        int cnt = wend - wbeg;

        #pragma unroll
        for (int i = 0; i < 8; i++)
            *(float2*)(arow + i * 66 + c) = make_float2(0.f, 0.f);

        for (int jb = 0; jb < cnt; jb += 32) {
            int ge = wbeg + jb + lane;
            int2 m = make_int2(0, 0);
            if (jb + lane < cnt) m = g_emeta[ge];
            int row = (ge >= b1) + (ge >= b2) + (ge >= b3) + (ge >= b4)
                    + (ge >= b5) + (ge >= b6) + (ge >= b7);
            int packed = m.x | (row << 20);
            int nrmi = m.y;
            int jmax = min(cnt - jb, 32);
            for (int j = 0; j < jmax; j += 4) {
                float2 v[4]; float nn[4]; int rw[4];
                #pragma unroll
                for (int k = 0; k < 4; k++) {
                    int jj = j + k;
                    int pk = __shfl_sync(0xFFFFFFFFu, packed, jj & 31);
                    int ni = __shfl_sync(0xFFFFFFFFu, nrmi, jj & 31);
                    nn[k] = (jj < jmax) ? __int_as_float(ni) : 0.f;
                    int s = pk & 0xFFFFF;
                    s = min(s, N_NODES - 1);
                    rw[k] = (pk >> 20) & 7;
                    v[k] = *(const float2*)(X + (size_t)s * 64 + c);
                }
                #pragma unroll
                for (int k = 0; k < 4; k++) {
                    float* ap = arow + rw[k] * 66 + c;
                    float2 f = *(float2*)ap;
                    f.x = fmaf(nn[k], v[k].x, f.x);
                    f.y = fmaf(nn[k], v[k].y, f.y);
                    *(float2*)ap = f;
                }
            }
        }

        __syncthreads();   // prior chunk's fragment reads complete

        // ===== convert own 8 rows fp32 -> bf16 hi/lo tiles =====
        #pragma unroll
        for (int i = 0; i < 8; i++) {
            float2 f = *(float2*)(arow + i * 66 + c);
            __nv_bfloat16 h0, l0, h1, l1;
            split_bf16(f.x, h0, l0);
            split_bf16(f.y, h1, l1);
            int row = warp * 8 + i;
            __nv_bfloat162 ph; ph.x = h0; ph.y = h1;
            __nv_bfloat162 pl; pl.x = l0; pl.y = l1;
            *(__nv_bfloat162*)(Ahi + row * NLDA + c) = ph;
            *(__nv_bfloat162*)(Alo + row * NLDA + c) = pl;
        }

        // ===== load B chunk (relation weights) =====
        for (int idx = tid; idx < 64 * 64; idx += 512) {
            int n = idx >> 6, k = idx & 63;
            Bhi[n * NLDA + k] = Wh[n * K_TOT + r * 64 + k];
            Blo[n * NLDA + k] = Wl[n * K_TOT + r * 64 + k];
        }
        __syncthreads();

        // ===== 3-pass MMA via ldmatrix (hi/lo fragments loaded once) =====
        #pragma unroll
        for (int ks = 0; ks < 4; ks++) {
            uint32_t kb = ks * 32;       // k0*2 bytes
            uint32_t aH0[4], aH1[4], aL0[4], aL1[4], bH[4], bL[4];
            ldsm4(aH0, aHiAddr + kb);
            ldsm4(aH1, aHiAddr + 16 * (NLDA * 2) + kb);
            ldsm4(aL0, aLoAddr + kb);
            ldsm4(aL1, aLoAddr + 16 * (NLDA * 2) + kb);
            ldsm4(bH, bHiAddr + kb);
            ldsm4(bL, bLoAddr + kb);
            mma16816(C[0], aH0, bH + 0); mma16816(C[1], aH0, bH + 2);
            mma16816(C[2], aH1, bH + 0); mma16816(C[3], aH1, bH + 2);
            mma16816(C[0], aL0, bH + 0); mma16816(C[1], aL0, bH + 2);
            mma16816(C[2], aL1, bH + 0); mma16816(C[3], aL1, bH + 2);
            mma16816(C[0], aH0, bL + 0); mma16816(C[1], aH0, bL + 2);
            mma16816(C[2], aH1, bL + 0); mma16816(C[3], aH1, bL + 2);
        }
    }

    // ===== epilogue =====
    int dorelu = (phase == 0);
    #pragma unroll
    for (int mt = 0; mt < 2; mt++) {
        int r0 = rb + wr + mt * 16 + g;
        int r1 = r0 + 8;
        #pragma unroll
        for (int nt = 0; nt < 2; nt++) {
            int gc = wc + nt * 8 + 2 * t;
            float b0 = bias[gc], b1 = bias[gc + 1];
            float c00 = C[mt * 2 + nt][0] + b0, c01 = C[mt * 2 + nt][1] + b1;
            float c10 = C[mt * 2 + nt][2] + b0, c11 = C[mt * 2 + nt][3] + b1;
            if (dorelu) {
                c00 = fmaxf(c00, 0.f); c01 = fmaxf(c01, 0.f);
                c10 = fmaxf(c10, 0.f); c11 = fmaxf(c11, 0.f);
            }
            if (r0 < N_NODES)
                *(float2*)(OP + (size_t)r0 * 64 + gc) = make_float2(c00, c01);
            if (r1 < N_NODES)
                *(float2*)(OP + (size_t)r1 * 64 + gc) = make_float2(c10, c11);
        }
    }
}

// ---------------- launch ----------------
extern "C" void kernel_launch(void* const* d_in, const int* in_sizes, int n_in,
                              void* d_out, int out_size) {
    const int* feat = (const int*)d_in[0];
    const int* src = (const int*)d_in[1];
    const int* dst = (const int*)d_in[2];
    const int* etype = (const int*)d_in[3];
    const float* norm = (const float*)d_in[4];
    const float* emb = (const float*)d_in[5];
    const float* smw = (const float*)d_in[6];
    const float* smb = (const float*)d_in[7];
    const float* V1 = (const float*)d_in[8];
    const float* c1 = (const float*)d_in[9];
    const float* b1 = (const float*)d_in[10];
    const float* V2 = (const float*)d_in[11];
    const float* c2 = (const float*)d_in[12];
    const float* b2 = (const float*)d_in[13];
    float* out = (float*)d_out;

    const int smemSM = (128 * NLDA * 2 + 64 * NLDA * 2) * 2 + 128 * 8 * 4;
    const int smemFU = (128 * NLDA * 2 + 64 * NLDA * 2) * 2 + 128 * 66 * 4;  // 89088
    static int attr_done = 0;
    if (!attr_done) {
        cudaFuncSetAttribute(k_front, cudaFuncAttributeMaxDynamicSharedMemorySize, smemSM);
        cudaFuncSetAttribute(k_fused, cudaFuncAttributeMaxDynamicSharedMemorySize, smemFU);
        attr_done = 1;
    }

    k_front<<<NB_SM + NB_PREPW + NB_HIST, 256, smemSM>>>(feat, emb, smw, smb,
                                                         V1, c1, V2, c2, dst, etype);
    k_scan<<<SCAN_NB, 1024>>>();
    k_scatter<<<NB_HIST, 256>>>(src, dst, etype, norm);
    k_fused<<<NB_SM, 512, smemFU>>>(0, b1, nullptr);      // ncu capture slot
    k_fused<<<NB_SM, 512, smemFU>>>(1, b2, out);
}